// round 8
// baseline (speedup 1.0000x reference)
#include <cuda_runtime.h>
#include <math.h>

#define NV 4096
#define EV 131072
#define EPS 1e-6f
#define EPSN 4.096e-3f   // EPS * NV

static __device__ float g_h1[NV*128];   // [gcn1 h | ptd1 y]
static __device__ float g_x1[NV*64];
static __device__ float g_h2[NV*48];    // [gcn2 h | ptd2 y]
static __device__ float g_xout[NV*16];
static __device__ float g_Wc1[512*128];
static __device__ float g_Wc2[64*48];
static __device__ float g_deg[2*NV], g_dis[NV], g_r[2*NV];
static __device__ float g_Y[NV*6], g_Qb[NV*6], g_Zb[NV*6], g_G[NV*6], g_V[NV*6];
static __device__ float g_cs[6], g_U6[36];
static __device__ float g_u[NV], g_t[NV], g_z[NV], g_vi[NV], g_c[NV], g_D[3][NV];
static __device__ float g_sc[16];
static __device__ double g_ds[8];

__device__ __forceinline__ float wsum(float v){
    #pragma unroll
    for (int o = 16; o; o >>= 1) v += __shfl_xor_sync(0xffffffffu, v, o);
    return v;
}

// block reduce n values (blockDim = 1024); result broadcast to all threads
__device__ void bred(float* vals, int n, float* sb){
    int w = threadIdx.x >> 5, l = threadIdx.x & 31;
    __syncthreads();
    for (int q = 0; q < n; q++){ float v = wsum(vals[q]); if (l == 0) sb[q*32 + w] = v; }
    __syncthreads();
    if (w == 0) for (int q = 0; q < n; q++){ float v = wsum(sb[q*32 + l]); if (l == 0) sb[q*32] = v; }
    __syncthreads();
    for (int q = 0; q < n; q++) vals[q] = sb[q*32];
}

__global__ void k_init(){
    int i = blockIdx.x*blockDim.x + threadIdx.x;
    if (i < 8)  g_ds[i] = 0.0;
    if (i < 16) g_sc[i] = 0.f;
    if (i < 2*NV){ g_deg[i] = 1.f; g_r[i] = 0.f; }
}

__global__ void k_catW(const float* __restrict__ wa, const float* __restrict__ wb, int mode){
    int K = mode?64:512, c1 = mode?16:64, c2 = mode?32:64, NC = c1+c2;
    float* W = mode ? g_Wc2 : g_Wc1;
    int i = blockIdx.x*blockDim.x + threadIdx.x;
    if (i >= K*NC) return;
    int row = i/NC, col = i%NC;
    W[i] = (col < c1) ? wa[row*c1+col] : wb[row*c2+(col-c1)];
}

__global__ void k_gemm(const float* __restrict__ Aext, int mode){
    const float* A = mode ? g_x1  : Aext;
    const float* B = mode ? g_Wc2 : g_Wc1;
    float*       C = mode ? g_h2  : g_h1;
    int K = mode?64:512, NC = mode?48:128;
    int row = blockIdx.y*8 + threadIdx.y;
    int tx = threadIdx.x;
    float acc[4] = {0,0,0,0};
    const float* ar = A + (size_t)row*K;
    for (int k = 0; k < K; k++){
        float a = ar[k];
        const float* br = B + (size_t)k*NC;
        #pragma unroll
        for (int c = 0; c < 4; c++){ int col = tx + 32*c; if (col < NC) acc[c] += a*br[col]; }
    }
    #pragma unroll
    for (int c = 0; c < 4; c++){ int col = tx + 32*c; if (col < NC) C[(size_t)row*NC+col] = acc[c]; }
}

__global__ void k_gate1(const float* __restrict__ b1, const float* __restrict__ w2,
                        const float* __restrict__ b2, const int* __restrict__ src,
                        const int* __restrict__ dst, float* __restrict__ sOut){
    int wid = (blockIdx.x*blockDim.x + threadIdx.x) >> 5, lane = threadIdx.x & 31;
    if (wid >= EV) return;
    int s = src[wid], d = dst[wid];
    const float* ys = g_h1 + (size_t)s*128 + 64;
    const float* yd = g_h1 + (size_t)d*128 + 64;
    float a = fmaxf(ys[lane]    - yd[lane]    + b1[lane],    0.f)*w2[lane]
            + fmaxf(ys[lane+32] - yd[lane+32] + b1[lane+32], 0.f)*w2[lane+32];
    a = wsum(a);
    if (lane == 0){
        a += b2[0]; a = a*a;
        float sv = 1.f/(1.f+expf(-a));
        sv = fminf(fmaxf(sv, 0.f), 1.f);
        sOut[wid] = sv;
        atomicAdd(&g_deg[d], sv);
        atomicAdd(&g_r[s], sv);
    }
}

__global__ void k_gate2(const float* __restrict__ b1, const float* __restrict__ w2,
                        const float* __restrict__ b2, const int* __restrict__ src,
                        const int* __restrict__ dst, float* __restrict__ sOut){
    int wid = (blockIdx.x*blockDim.x + threadIdx.x) >> 5, lane = threadIdx.x & 31;
    if (wid >= EV) return;
    int s = src[wid], d = dst[wid];
    const float* ys = g_h2 + (size_t)s*48 + 16;
    const float* yd = g_h2 + (size_t)d*48 + 16;
    float a = fmaxf(ys[lane] - yd[lane] + b1[lane], 0.f)*w2[lane];
    a = wsum(a);
    if (lane == 0){
        a += b2[0]; a = a*a;
        float sv = 1.f/(1.f+expf(-a));
        sv = fminf(fmaxf(sv, 0.f), 1.f);
        sOut[wid] = sv;
        atomicAdd(&g_deg[NV + d], sv);
        atomicAdd(&g_r[NV + s], sv);
    }
}

__global__ void k_sumS(const float* __restrict__ s, int off){
    __shared__ double sd[512];
    double a = 0, b = 0;
    for (int i = blockIdx.x*blockDim.x + threadIdx.x; i < EV; i += gridDim.x*blockDim.x){
        double v = s[i]; a += v; b += v*v;
    }
    sd[threadIdx.x] = a; sd[256 + threadIdx.x] = b; __syncthreads();
    for (int o = 128; o; o >>= 1){
        if (threadIdx.x < o){ sd[threadIdx.x] += sd[threadIdx.x+o]; sd[256+threadIdx.x] += sd[256+threadIdx.x+o]; }
        __syncthreads();
    }
    if (threadIdx.x == 0){ atomicAdd(&g_ds[off], sd[0]); atomicAdd(&g_ds[off+1], sd[256]); }
}

__global__ void k_dis(int sel){
    int i = blockIdx.x*blockDim.x + threadIdx.x;
    if (i < NV) g_dis[i] = rsqrtf(g_deg[sel*NV + i]);
}

__global__ void k_gself(int conv){
    int i = blockIdx.x*blockDim.x + threadIdx.x;
    if (conv == 0){
        if (i < NV*64){ int row = i>>6; float di = g_dis[row]; g_x1[i] = di*di*g_h1[(size_t)row*128 + (i&63)]; }
    } else {
        if (i < NV*16){ int row = i>>4; float di = g_dis[row]; g_xout[i] = di*di*g_h2[(size_t)row*48 + (i&15)]; }
    }
}

__global__ void k_gscat(int conv, const int* __restrict__ src, const int* __restrict__ dst,
                        const float* __restrict__ w){
    int wid = (blockIdx.x*blockDim.x + threadIdx.x) >> 5, lane = threadIdx.x & 31;
    if (wid >= EV) return;
    int s = src[wid], d = dst[wid];
    float cf = g_dis[s]*w[wid]*g_dis[d];
    if (conv == 0){
        atomicAdd(&g_x1[(size_t)d*64 + lane],      cf*g_h1[(size_t)s*128 + lane]);
        atomicAdd(&g_x1[(size_t)d*64 + lane + 32], cf*g_h1[(size_t)s*128 + lane + 32]);
    } else if (lane < 16){
        atomicAdd(&g_xout[(size_t)d*16 + lane], cf*g_h2[(size_t)s*48 + lane]);
    }
}

__global__ void k_gpost(int conv, const float* __restrict__ b){
    int i = blockIdx.x*blockDim.x + threadIdx.x;
    if (conv == 0){ if (i < NV*64) g_x1[i] = fmaxf(g_x1[i] + b[i&63], 0.f); }
    else          { if (i < NV*16) g_xout[i] += b[i&15]; }
}

__global__ void k_softmax(float* __restrict__ lsm, float* __restrict__ sm){
    __shared__ float sr[256];
    int row = blockIdx.x*256 + threadIdx.x;
    float v[16], m1 = -1e30f;
    #pragma unroll
    for (int c = 0; c < 16; c++){ v[c] = g_xout[row*16+c]; m1 = fmaxf(m1, v[c]); }
    float m2 = -1e30f; int seen = 0;
    #pragma unroll
    for (int c = 0; c < 16; c++){
        if (v[c] == m1 && !seen){ seen = 1; continue; }
        m2 = fmaxf(m2, v[c]);
    }
    float se = 0;
    #pragma unroll
    for (int c = 0; c < 16; c++) se += expf(v[c]-m1);
    float ls = logf(se);
    #pragma unroll
    for (int c = 0; c < 16; c++){ lsm[row*16+c] = v[c]-m1-ls; sm[row*16+c] = expf(v[c]-m1)/se; }
    sr[threadIdx.x] = m2 - m1; __syncthreads();
    for (int o = 128; o; o >>= 1){ if (threadIdx.x < o) sr[threadIdx.x] += sr[threadIdx.x+o]; __syncthreads(); }
    if (threadIdx.x == 0) atomicAdd(&g_sc[8], sr[0]);
}

// ---------------- SVD (A = S + eps*J, implicit) ----------------
__device__ __forceinline__ const float* pickM(const float* ext, int ms){
    return ms == 0 ? g_Qb : (ms == 1 ? g_Zb : ext);
}

__global__ void k_prep6(const float* ext, int ms){
    __shared__ float sb[192];
    const float* M = pickM(ext, ms);
    float p[6] = {0,0,0,0,0,0};
    for (int i = threadIdx.x; i < NV; i += 1024)
        #pragma unroll
        for (int j = 0; j < 6; j++) p[j] += M[i*6+j];
    bred(p, 6, sb);
    if (threadIdx.x < 6) g_cs[threadIdx.x] = p[threadIdx.x];
    for (int i = threadIdx.x; i < NV*6; i += 1024) g_Y[i] = 0.f;
}

// tr=0: Y[src]+=w*M[dst] (S@M) ; tr=1: Y[dst]+=w*M[src] (S^T@M)
__global__ void k_scat6(const float* ext, int ms, const float* __restrict__ w,
                        const int* __restrict__ src, const int* __restrict__ dst, int tr){
    int e = blockIdx.x*blockDim.x + threadIdx.x;
    if (e >= EV) return;
    const float* M = pickM(ext, ms);
    int s = src[e], d = dst[e]; float we = w[e];
    int from = tr ? s : d, to = tr ? d : s;
    const float* mr = M + (size_t)from*6;
    float* yr = g_Y + (size_t)to*6;
    #pragma unroll
    for (int j = 0; j < 6; j++) atomicAdd(&yr[j], we*mr[j]);
}

__global__ void k_qr(int qs){
    __shared__ float sb[192];
    float* Q = qs ? g_Zb : g_Qb;
    int tid = threadIdx.x;
    float v[4][6];
    #pragma unroll
    for (int rr = 0; rr < 4; rr++){ int i = tid + rr*1024;
        #pragma unroll
        for (int j = 0; j < 6; j++) v[rr][j] = g_Y[i*6+j] + EPS*g_cs[j]; }
    for (int j = 0; j < 6; j++){
        for (int pass = 0; pass < 2 && j > 0; pass++){
            float h[5];
            for (int q = 0; q < j; q++){
                float s = 0;
                #pragma unroll
                for (int rr = 0; rr < 4; rr++) s += v[rr][q]*v[rr][j];
                h[q] = s;
            }
            bred(h, j, sb);
            for (int q = 0; q < j; q++)
                #pragma unroll
                for (int rr = 0; rr < 4; rr++) v[rr][j] -= h[q]*v[rr][q];
        }
        float n2 = 0;
        #pragma unroll
        for (int rr = 0; rr < 4; rr++) n2 += v[rr][j]*v[rr][j];
        bred(&n2, 1, sb);
        float sc = 1.f/sqrtf(fmaxf(n2, 1e-30f));
        #pragma unroll
        for (int rr = 0; rr < 4; rr++) v[rr][j] *= sc;
    }
    #pragma unroll
    for (int rr = 0; rr < 4; rr++){ int i = tid + rr*1024;
        #pragma unroll
        for (int j = 0; j < 6; j++) Q[i*6+j] = v[rr][j]; }
}

__global__ void k_finB(){
    __shared__ float sb[192];
    int tid = threadIdx.x;
    float g[4][6];
    #pragma unroll
    for (int rr = 0; rr < 4; rr++){ int i = tid + rr*1024;
        #pragma unroll
        for (int j = 0; j < 6; j++){ float vv = g_Y[i*6+j] + EPS*g_cs[j]; g[rr][j] = vv; g_G[i*6+j] = vv; } }
    float p[21]; int id = 0;
    for (int a = 0; a < 6; a++)
        for (int b = a; b < 6; b++){
            float s = 0;
            #pragma unroll
            for (int rr = 0; rr < 4; rr++) s += g[rr][a]*g[rr][b];
            p[id++] = s;
        }
    bred(p, 6, sb); bred(p+6, 6, sb); bred(p+12, 6, sb); bred(p+18, 3, sb);
    if (tid == 0){
        double A[6][6], Vv[6][6]; id = 0;
        for (int a = 0; a < 6; a++) for (int b = a; b < 6; b++){ A[a][b] = p[id]; A[b][a] = p[id]; id++; }
        for (int a = 0; a < 6; a++) for (int b = 0; b < 6; b++) Vv[a][b] = (a==b) ? 1.0 : 0.0;
        for (int sw = 0; sw < 30; sw++)
            for (int pp = 0; pp < 5; pp++) for (int q = pp+1; q < 6; q++){
                double apq = A[pp][q]; if (fabs(apq) < 1e-30) continue;
                double tau = (A[q][q]-A[pp][pp])/(2.0*apq);
                double t = (tau >= 0 ? 1.0 : -1.0)/(fabs(tau)+sqrt(1.0+tau*tau));
                double c = 1.0/sqrt(1.0+t*t), s = t*c;
                for (int i = 0; i < 6; i++){ double a1=A[i][pp],a2=A[i][q]; A[i][pp]=c*a1-s*a2; A[i][q]=s*a1+c*a2; }
                for (int i = 0; i < 6; i++){ double a1=A[pp][i],a2=A[q][i]; A[pp][i]=c*a1-s*a2; A[q][i]=s*a1+c*a2; }
                for (int i = 0; i < 6; i++){ double a1=Vv[i][pp],a2=Vv[i][q]; Vv[i][pp]=c*a1-s*a2; Vv[i][q]=s*a1+c*a2; }
            }
        int ord[6] = {0,1,2,3,4,5};
        for (int a = 0; a < 6; a++) for (int b = a+1; b < 6; b++)
            if (A[ord[b]][ord[b]] > A[ord[a]][ord[a]]){ int t2 = ord[a]; ord[a] = ord[b]; ord[b] = t2; }
        for (int kk = 0; kk < 6; kk++) for (int j = 0; j < 6; j++) g_U6[j*6+kk] = (float)Vv[j][ord[kk]];
    }
}

__global__ void k_compV(){
    int i = blockIdx.x*blockDim.x + threadIdx.x;
    if (i >= NV) return;
    float gr[6];
    #pragma unroll
    for (int j = 0; j < 6; j++) gr[j] = g_G[i*6+j];
    #pragma unroll
    for (int kk = 0; kk < 6; kk++){
        float s = 0;
        #pragma unroll
        for (int j = 0; j < 6; j++) s += gr[j]*g_U6[j*6+kk];
        g_V[i*6+kk] = s;
    }
}

// ---------------- nuclear loss ----------------
__global__ void k_resetc(){
    int i = blockIdx.x*blockDim.x + threadIdx.x;
    if (i < NV) g_c[i] = 1.f;
}

__global__ void k_prepu(int k, int nd, int em, int rs){
    __shared__ float sb[192];
    int tid = threadIdx.x;
    float u[4];
    #pragma unroll
    for (int rr = 0; rr < 4; rr++){ int i = tid + rr*1024; u[rr] = g_V[i*6+k]; if (em) u[rr] *= g_c[i]; }
    if (!em){
        for (int j = nd-1; j >= 0; j--){
            float d = 0;
            #pragma unroll
            for (int rr = 0; rr < 4; rr++) d += g_D[j][tid+rr*1024]*u[rr];
            bred(&d, 1, sb);
            #pragma unroll
            for (int rr = 0; rr < 4; rr++) u[rr] -= d*g_D[j][tid+rr*1024];
        }
    }
    float s2[2] = {0,0};
    #pragma unroll
    for (int rr = 0; rr < 4; rr++){ int i = tid + rr*1024; s2[0] += u[rr]; s2[1] += g_r[rs*NV+i]*u[rr]; }
    bred(s2, 2, sb);
    #pragma unroll
    for (int rr = 0; rr < 4; rr++){
        int i = tid + rr*1024;
        g_u[i] = u[rr]; g_t[i] = 0.f;
        g_z[i] = EPS*(s2[0]*g_r[rs*NV+i] + s2[1] + EPSN*s2[0]);
    }
}

__global__ void k_scatT(const float* __restrict__ w, const int* __restrict__ src, const int* __restrict__ dst){
    int e = blockIdx.x*blockDim.x + threadIdx.x;
    if (e >= EV) return;
    atomicAdd(&g_t[dst[e]], w[e]*g_u[src[e]]);
}

__global__ void k_scatZ(const float* __restrict__ w, const int* __restrict__ src, const int* __restrict__ dst){
    int e = blockIdx.x*blockDim.x + threadIdx.x;
    if (e >= EV) return;
    atomicAdd(&g_z[src[e]], w[e]*g_t[dst[e]]);
}

__global__ void k_mid(int nd, int em, int rs){
    __shared__ float sb[192];
    int tid = threadIdx.x;
    float v[4], n2 = 0;
    #pragma unroll
    for (int rr = 0; rr < 4; rr++){ int i = tid + rr*1024; float z = g_z[i]; if (em) z *= g_c[i]; v[rr] = z; n2 += z*z; }
    bred(&n2, 1, sb);
    float inv = 1.f/sqrtf(fmaxf(n2, 1e-30f));
    float u[4];
    #pragma unroll
    for (int rr = 0; rr < 4; rr++){
        int i = tid + rr*1024;
        v[rr] *= inv; g_vi[i] = v[rr];
        u[rr] = em ? v[rr]*g_c[i] : v[rr];
    }
    if (!em){
        for (int j = nd-1; j >= 0; j--){
            float d = 0;
            #pragma unroll
            for (int rr = 0; rr < 4; rr++) d += g_D[j][tid+rr*1024]*u[rr];
            bred(&d, 1, sb);
            #pragma unroll
            for (int rr = 0; rr < 4; rr++) u[rr] -= d*g_D[j][tid+rr*1024];
        }
    }
    float s2[2] = {0,0};
    #pragma unroll
    for (int rr = 0; rr < 4; rr++){ int i = tid + rr*1024; s2[0] += u[rr]; s2[1] += g_r[rs*NV+i]*u[rr]; }
    bred(s2, 2, sb);
    #pragma unroll
    for (int rr = 0; rr < 4; rr++){
        int i = tid + rr*1024;
        g_u[i] = u[rr]; g_t[i] = 0.f;
        g_z[i] = EPS*(s2[0]*g_r[rs*NV+i] + s2[1] + EPSN*s2[0]);
    }
}

__global__ void k_fin(int em, int slot){
    __shared__ float sb[192];
    int tid = threadIdx.x;
    float s2[2] = {0,0};
    #pragma unroll
    for (int rr = 0; rr < 4; rr++){
        int i = tid + rr*1024;
        float vi = g_vi[i];
        float sel = em ? g_u[i] : vi;
        s2[0] += sel*g_z[i]; s2[1] += vi*vi;
    }
    bred(s2, 2, sb);
    if (tid == 0) g_sc[5] += sqrtf(fabsf(s2[0]/s2[1]));
    if (slot >= 0){
        #pragma unroll
        for (int rr = 0; rr < 4; rr++){
            int i = tid + rr*1024;
            if (em) g_c[i] *= g_vi[i];
            else    g_D[slot][i] = g_vi[i];
        }
    }
}

__global__ void k_final(float* loss, float* calib){
    double E = (double)EV;
    double c1 = g_ds[1]/E - (g_ds[0]/E)*(g_ds[0]/E);
    double c2 = g_ds[3]/E - (g_ds[2]/E)*(g_ds[2]/E);
    *loss  = (float)(0.01*(c1+c2) + 0.01*(double)g_sc[5]);
    *calib = g_sc[8]/(float)NV;
}

extern "C" void kernel_launch(void* const* d_in, const int* in_sizes, int n_in,
                              void* d_out, int out_size){
    const float* x     = (const float*)d_in[0];
    const int*   ei    = (const int*)d_in[1];
    const int*   src   = ei;
    const int*   dst   = ei + EV;
    const float* gcn1w = (const float*)d_in[2];
    const float* gcn1b = (const float*)d_in[3];
    const float* gcn2w = (const float*)d_in[4];
    const float* gcn2b = (const float*)d_in[5];
    const float* p1w1  = (const float*)d_in[6];
    const float* p1b1  = (const float*)d_in[7];
    const float* p1w2  = (const float*)d_in[8];
    const float* p1b2  = (const float*)d_in[9];
    const float* p2w1  = (const float*)d_in[10];
    const float* p2b1  = (const float*)d_in[11];
    const float* p2w2  = (const float*)d_in[12];
    const float* p2b2  = (const float*)d_in[13];
    const float* om1   = (const float*)d_in[14];
    const float* om2   = (const float*)d_in[15];

    float* out   = (float*)d_out;
    float* lsm   = out;
    float* sm    = out + NV*16;
    float* loss  = out + 2*NV*16;
    float* s1    = out + 2*NV*16 + 1;
    float* s2    = s1 + EV;
    float* calib = s2 + EV;

    k_init<<<32,256>>>();
    k_catW<<<(512*128+255)/256,256>>>(gcn1w, p1w1, 0);
    k_catW<<<(64*48+255)/256,256>>>(gcn2w, p2w1, 1);
    k_gemm<<<dim3(1,512),dim3(32,8)>>>(x, 0);
    k_gate1<<<EV/8,256>>>(p1b1, p1w2, p1b2, src, dst, s1);
    k_sumS<<<64,256>>>(s1, 0);
    k_dis<<<16,256>>>(0);
    k_gself<<<NV*64/256,256>>>(0);
    k_gscat<<<EV/8,256>>>(0, src, dst, s1);
    k_gpost<<<NV*64/256,256>>>(0, gcn1b);
    k_gemm<<<dim3(1,512),dim3(32,8)>>>(x, 1);
    k_gate2<<<EV/8,256>>>(p2b1, p2w2, p2b2, src, dst, s2);
    k_sumS<<<64,256>>>(s2, 2);
    k_dis<<<16,256>>>(1);
    k_gself<<<NV*16/256,256>>>(1);
    k_gscat<<<EV/8,256>>>(1, src, dst, s2);
    k_gpost<<<NV*16/256,256>>>(1, gcn2b);
    k_softmax<<<16,256>>>(lsm, sm);

    for (int v = 0; v < 2; v++){
        const float* w  = v ? s2  : s1;
        const float* om = v ? om2 : om1;
        int rs = v;
        int em = (v == 0);  // variant 0: elementwise deflation; variant 1: matmul deflation

        // randomized SVD range finder (niter = 2)
        k_prep6<<<1,1024>>>(om, 2);
        k_scat6<<<EV/256,256>>>(om, 2, w, src, dst, 0);
        k_qr<<<1,1024>>>(0);
        for (int it = 0; it < 2; it++){
            k_prep6<<<1,1024>>>(nullptr, 0);
            k_scat6<<<EV/256,256>>>(nullptr, 0, w, src, dst, 1);
            k_qr<<<1,1024>>>(1);
            k_prep6<<<1,1024>>>(nullptr, 1);
            k_scat6<<<EV/256,256>>>(nullptr, 1, w, src, dst, 0);
            k_qr<<<1,1024>>>(0);
        }
        k_prep6<<<1,1024>>>(nullptr, 0);
        k_scat6<<<EV/256,256>>>(nullptr, 0, w, src, dst, 1);
        k_finB<<<1,1024>>>();
        k_compV<<<16,256>>>();

        // nuclear-norm proxy with sequential deflation
        k_resetc<<<16,256>>>();
        for (int k = 0; k < 6; k++){
            int nd = k - 2; if (nd < 0) nd = 0; if (nd > 3) nd = 3;
            k_prepu<<<1,1024>>>(k, nd, em, rs);
            k_scatT<<<EV/256,256>>>(w, src, dst);
            k_scatZ<<<EV/256,256>>>(w, src, dst);
            k_mid<<<1,1024>>>(nd, em, rs);
            k_scatT<<<EV/256,256>>>(w, src, dst);
            k_scatZ<<<EV/256,256>>>(w, src, dst);
            int slot = (k >= 2 && k <= 4) ? k-2 : -1;
            k_fin<<<1,1024>>>(em, slot);
        }
    }
    k_final<<<1,1>>>(loss, calib);
}

// round 11
// speedup vs baseline: 2.0319x; 2.0319x over previous
#include <cuda_runtime.h>
#include <math.h>

#define NV 4096
#define EV 131072
#define EPS 1e-6f
#define EPSN 4.096e-3f   // EPS * NV

// ---------------- static device scratch ----------------
static __device__ float g_h1[NV*128];   // [gcn1 h | ptd1 y]
static __device__ float g_x1[NV*64];
static __device__ float g_h2[NV*48];    // [gcn2 h | ptd2 y]
static __device__ float g_xout[NV*16];
static __device__ float g_Wc1[512*128];
static __device__ float g_Wc2[64*48];
static __device__ float g_deg[2*NV], g_r[2*NV];
static __device__ int   g_cntd[NV], g_cnts[NV];
static __device__ int   g_startd[NV+1], g_starts[NV+1];
static __device__ int   g_curd[NV], g_curs[NV];
static __device__ int   g_adj_d_src[EV], g_adj_d_eid[EV];
static __device__ int   g_adj_s_dst[EV], g_adj_s_eid[EV];
static __device__ float g_Y[2][NV*6], g_Qb[2][NV*6], g_Zb[2][NV*6], g_V[2][NV*6];
static __device__ float g_cs[2][6], g_U6[2][36];
static __device__ float g_UU[2][NV], g_TT[2][NV], g_ZZ[2][NV];
static __device__ float g_c[NV], g_D[3][NV], g_vi[2][NV];
static __device__ float g_sm[2][2];
static __device__ float g_nuc[2];
static __device__ double g_ds[8];

__device__ __forceinline__ float wsum(float v){
    #pragma unroll
    for (int o = 16; o; o >>= 1) v += __shfl_xor_sync(0xffffffffu, v, o);
    return v;
}

// block reduce n<=16 values (blockDim = 1024); broadcast to all threads
__device__ void bred(float* vals, int n, float* sb /*>=512*/){
    int w = threadIdx.x >> 5, l = threadIdx.x & 31;
    __syncthreads();
    for (int q = 0; q < n; q++){ float v = wsum(vals[q]); if (l == 0) sb[q*32 + w] = v; }
    __syncthreads();
    if (w == 0) for (int q = 0; q < n; q++){ float v = wsum(sb[q*32 + l]); if (l == 0) sb[q*32] = v; }
    __syncthreads();
    for (int q = 0; q < n; q++) vals[q] = sb[q*32];
}

// ---------------- init ----------------
__global__ void k_init(){
    int i = blockIdx.x*blockDim.x + threadIdx.x;
    if (i < 8)  g_ds[i] = 0.0;
    if (i < 2)  g_nuc[i] = 0.f;
    if (i < NV){ g_cntd[i] = 0; g_cnts[i] = 0; }
    if (i < 2*NV){ g_deg[i] = 1.f; g_r[i] = 0.f; }
}

// ---------------- CSR build ----------------
__global__ void k_hist(const int* __restrict__ src, const int* __restrict__ dst){
    int e = blockIdx.x*blockDim.x + threadIdx.x;
    if (e >= EV) return;
    atomicAdd(&g_cntd[dst[e]], 1);
    atomicAdd(&g_cnts[src[e]], 1);
}

__global__ void __launch_bounds__(1024) k_scan(){
    __shared__ int wt[32];
    int t = threadIdx.x, lane = t & 31, w = t >> 5;
    for (int a = 0; a < 2; a++){
        const int* cnt = a ? g_cnts : g_cntd;
        int* start = a ? g_starts : g_startd;
        int* cur   = a ? g_curs  : g_curd;
        int c[4]; int s = 0;
        #pragma unroll
        for (int q = 0; q < 4; q++){ c[q] = cnt[t*4+q]; s += c[q]; }
        int v = s;
        #pragma unroll
        for (int o = 1; o < 32; o <<= 1){ int n = __shfl_up_sync(~0u, v, o); if (lane >= o) v += n; }
        if (lane == 31) wt[w] = v;
        __syncthreads();
        if (w == 0){
            int x = wt[lane];
            #pragma unroll
            for (int o = 1; o < 32; o <<= 1){ int n = __shfl_up_sync(~0u, x, o); if (lane >= o) x += n; }
            wt[lane] = x;
        }
        __syncthreads();
        int run = v - s + (w ? wt[w-1] : 0);
        #pragma unroll
        for (int q = 0; q < 4; q++){ start[t*4+q] = run; cur[t*4+q] = run; run += c[q]; }
        if (t == 1023) start[NV] = run;
        __syncthreads();
    }
}

__global__ void k_csr(const int* __restrict__ src, const int* __restrict__ dst){
    int e = blockIdx.x*blockDim.x + threadIdx.x;
    if (e >= EV) return;
    int s = src[e], d = dst[e];
    int pd = atomicAdd(&g_curd[d], 1);
    g_adj_d_src[pd] = s; g_adj_d_eid[pd] = e;
    int ps = atomicAdd(&g_curs[s], 1);
    g_adj_s_dst[ps] = d; g_adj_s_eid[ps] = e;
}

// ---------------- weight concat + tiled GEMM ----------------
__global__ void k_catW(const float* __restrict__ wa, const float* __restrict__ wb, int mode){
    int K = mode?64:512, c1 = mode?16:64, c2 = mode?32:64, NC = c1+c2;
    float* W = mode ? g_Wc2 : g_Wc1;
    int i = blockIdx.x*blockDim.x + threadIdx.x;
    if (i >= K*NC) return;
    int row = i/NC, col = i%NC;
    W[i] = (col < c1) ? wa[row*c1+col] : wb[row*c2+(col-c1)];
}

__global__ void k_gemm(const float* __restrict__ Aext, int mode){
    const float* A = mode ? g_x1  : Aext;
    const float* B = mode ? g_Wc2 : g_Wc1;
    float*       C = mode ? g_h2  : g_h1;
    int K = mode?64:512, NC = mode?48:128;
    __shared__ float As[16][65];
    __shared__ float Bs[16][68];
    int tid = threadIdx.x;
    int tx = tid & 15, ty = tid >> 4;
    int m0 = blockIdx.y*64, n0 = blockIdx.x*64;
    float acc[4][4];
    #pragma unroll
    for (int r = 0; r < 4; r++)
        #pragma unroll
        for (int c = 0; c < 4; c++) acc[r][c] = 0.f;
    for (int k0 = 0; k0 < K; k0 += 16){
        {
            int m = tid >> 2, kk0 = (tid & 3)*4;
            const float* ap = &A[(size_t)(m0+m)*K + k0 + kk0];
            #pragma unroll
            for (int q = 0; q < 4; q++) As[kk0+q][m] = ap[q];
        }
        {
            int kk = tid >> 4, nn0 = (tid & 15)*4;
            #pragma unroll
            for (int q = 0; q < 4; q++){
                int n = n0 + nn0 + q;
                Bs[kk][nn0+q] = (n < NC) ? B[(size_t)(k0+kk)*NC + n] : 0.f;
            }
        }
        __syncthreads();
        #pragma unroll
        for (int kk = 0; kk < 16; kk++){
            float a[4], b[4];
            #pragma unroll
            for (int r = 0; r < 4; r++) a[r] = As[kk][ty*4+r];
            #pragma unroll
            for (int c = 0; c < 4; c++) b[c] = Bs[kk][tx*4+c];
            #pragma unroll
            for (int r = 0; r < 4; r++)
                #pragma unroll
                for (int c = 0; c < 4; c++) acc[r][c] += a[r]*b[c];
        }
        __syncthreads();
    }
    #pragma unroll
    for (int r = 0; r < 4; r++){
        int m = m0 + ty*4 + r;
        #pragma unroll
        for (int c = 0; c < 4; c++){
            int n = n0 + tx*4 + c;
            if (n < NC) C[(size_t)m*NC + n] = acc[r][c];
        }
    }
}

// ---------------- edge gates ----------------
__global__ void k_gate1(const float* __restrict__ b1, const float* __restrict__ w2,
                        const float* __restrict__ b2, const int* __restrict__ src,
                        const int* __restrict__ dst, float* __restrict__ sOut){
    int wid = (blockIdx.x*blockDim.x + threadIdx.x) >> 5, lane = threadIdx.x & 31;
    if (wid >= EV) return;
    int s = src[wid], d = dst[wid];
    const float* ys = g_h1 + (size_t)s*128 + 64;
    const float* yd = g_h1 + (size_t)d*128 + 64;
    float a = fmaxf(ys[lane]    - yd[lane]    + b1[lane],    0.f)*w2[lane]
            + fmaxf(ys[lane+32] - yd[lane+32] + b1[lane+32], 0.f)*w2[lane+32];
    a = wsum(a);
    if (lane == 0){
        a += b2[0]; a = a*a;
        float sv = 1.f/(1.f+expf(-a));
        sv = fminf(fmaxf(sv, 0.f), 1.f);
        sOut[wid] = sv;
        atomicAdd(&g_deg[d], sv);
        atomicAdd(&g_r[s], sv);
    }
}

__global__ void k_gate2(const float* __restrict__ b1, const float* __restrict__ w2,
                        const float* __restrict__ b2, const int* __restrict__ src,
                        const int* __restrict__ dst, float* __restrict__ sOut){
    int wid = (blockIdx.x*blockDim.x + threadIdx.x) >> 5, lane = threadIdx.x & 31;
    if (wid >= EV) return;
    int s = src[wid], d = dst[wid];
    const float* ys = g_h2 + (size_t)s*48 + 16;
    const float* yd = g_h2 + (size_t)d*48 + 16;
    float a = fmaxf(ys[lane] - yd[lane] + b1[lane], 0.f)*w2[lane];
    a = wsum(a);
    if (lane == 0){
        a += b2[0]; a = a*a;
        float sv = 1.f/(1.f+expf(-a));
        sv = fminf(fmaxf(sv, 0.f), 1.f);
        sOut[wid] = sv;
        atomicAdd(&g_deg[NV+d], sv);
        atomicAdd(&g_r[NV+s], sv);
    }
}

__global__ void k_sumS(const float* __restrict__ s, int off){
    __shared__ double sd[512];
    double a = 0, b = 0;
    for (int i = blockIdx.x*blockDim.x + threadIdx.x; i < EV; i += gridDim.x*blockDim.x){
        double v = s[i]; a += v; b += v*v;
    }
    sd[threadIdx.x] = a; sd[256+threadIdx.x] = b; __syncthreads();
    for (int o = 128; o; o >>= 1){
        if (threadIdx.x < o){ sd[threadIdx.x] += sd[threadIdx.x+o]; sd[256+threadIdx.x] += sd[256+threadIdx.x+o]; }
        __syncthreads();
    }
    if (threadIdx.x == 0){ atomicAdd(&g_ds[off], sd[0]); atomicAdd(&g_ds[off+1], sd[256]); }
}

// ---------------- fused GCN aggregation (gather by dst) ----------------
__global__ void k_gcn0(const float* __restrict__ b, const float* __restrict__ w){
    int d = (blockIdx.x*blockDim.x + threadIdx.x) >> 5, lane = threadIdx.x & 31;
    if (d >= NV) return;
    float degd = g_deg[d], did = rsqrtf(degd);
    float a0 = (1.f/degd)*g_h1[(size_t)d*128 + lane];
    float a1 = (1.f/degd)*g_h1[(size_t)d*128 + lane + 32];
    int p1 = g_startd[d+1];
    for (int p = g_startd[d]; p < p1; p++){
        int s = g_adj_d_src[p]; int e = g_adj_d_eid[p];
        float cf = rsqrtf(g_deg[s])*w[e]*did;
        a0 += cf*g_h1[(size_t)s*128 + lane];
        a1 += cf*g_h1[(size_t)s*128 + lane + 32];
    }
    g_x1[(size_t)d*64 + lane]      = fmaxf(a0 + b[lane],      0.f);
    g_x1[(size_t)d*64 + lane + 32] = fmaxf(a1 + b[lane + 32], 0.f);
}

__global__ void k_gcn1(const float* __restrict__ b, const float* __restrict__ w){
    int d = (blockIdx.x*blockDim.x + threadIdx.x) >> 5, lane = threadIdx.x & 31;
    if (d >= NV || lane >= 16) return;
    float degd = g_deg[NV+d], did = rsqrtf(degd);
    float a0 = (1.f/degd)*g_h2[(size_t)d*48 + lane];
    int p1 = g_startd[d+1];
    for (int p = g_startd[d]; p < p1; p++){
        int s = g_adj_d_src[p]; int e = g_adj_d_eid[p];
        float cf = rsqrtf(g_deg[NV+s])*w[e]*did;
        a0 += cf*g_h2[(size_t)s*48 + lane];
    }
    g_xout[(size_t)d*16 + lane] = a0 + b[lane];
}

// ---------------- softmax / log_softmax / calib ----------------
__global__ void k_softmax(float* __restrict__ lsm, float* __restrict__ sm){
    __shared__ double sr[256];
    int row = blockIdx.x*256 + threadIdx.x;
    float v[16], m1 = -1e30f;
    #pragma unroll
    for (int c = 0; c < 16; c++){ v[c] = g_xout[row*16+c]; m1 = fmaxf(m1, v[c]); }
    float m2 = -1e30f; int seen = 0;
    #pragma unroll
    for (int c = 0; c < 16; c++){
        if (v[c] == m1 && !seen){ seen = 1; continue; }
        m2 = fmaxf(m2, v[c]);
    }
    float se = 0;
    #pragma unroll
    for (int c = 0; c < 16; c++) se += expf(v[c]-m1);
    float ls = logf(se);
    #pragma unroll
    for (int c = 0; c < 16; c++){ lsm[row*16+c] = v[c]-m1-ls; sm[row*16+c] = expf(v[c]-m1)/se; }
    sr[threadIdx.x] = (double)(m2 - m1); __syncthreads();
    for (int o = 128; o; o >>= 1){ if (threadIdx.x < o) sr[threadIdx.x] += sr[threadIdx.x+o]; __syncthreads(); }
    if (threadIdx.x == 0) atomicAdd(&g_ds[6], sr[0]);
}

// ---------------- SVD: A = S + eps*J, implicit ----------------
__global__ void __launch_bounds__(1024) k_csext(const float* __restrict__ om1, const float* __restrict__ om2){
    __shared__ float sb[512];
    const float* M = blockIdx.x ? om2 : om1;
    float p[6] = {0,0,0,0,0,0};
    for (int i = threadIdx.x; i < NV; i += 1024)
        #pragma unroll
        for (int j = 0; j < 6; j++) p[j] += M[i*6+j];
    bred(p, 6, sb);
    if (threadIdx.x < 6) g_cs[blockIdx.x][threadIdx.x] = p[threadIdx.x];
}

// ms: 0=Qb, 1=Zb, 2=ext. tr=0: Y[n]=sum_{src=n} w*M[dst] (A@M). tr=1: Y[n]=sum_{dst=n} w*M[src] (A^T@M)
__global__ void k_g6(const float* __restrict__ om1, const float* __restrict__ om2, int ms, int tr,
                     const float* __restrict__ w1, const float* __restrict__ w2){
    int n = (blockIdx.x*blockDim.x + threadIdx.x) >> 5, lane = threadIdx.x & 31;
    int v = blockIdx.y;
    if (n >= NV) return;
    const float* M = (ms == 0) ? g_Qb[v] : (ms == 1) ? g_Zb[v] : (v ? om2 : om1);
    const float* w = v ? w2 : w1;
    const int* st    = tr ? g_startd    : g_starts;
    const int* other = tr ? g_adj_d_src : g_adj_s_dst;
    const int* eid   = tr ? g_adj_d_eid : g_adj_s_eid;
    float acc[6] = {0,0,0,0,0,0};
    int p1 = st[n+1];
    for (int p = st[n] + lane; p < p1; p += 32){
        float we = w[eid[p]];
        const float* mr = M + (size_t)other[p]*6;
        #pragma unroll
        for (int j = 0; j < 6; j++) acc[j] += we*mr[j];
    }
    #pragma unroll
    for (int j = 0; j < 6; j++) acc[j] = wsum(acc[j]);
    if (lane == 0)
        #pragma unroll
        for (int j = 0; j < 6; j++) g_Y[v][n*6+j] = acc[j] + EPS*g_cs[v][j];
}

// CGS2 QR of g_Y[v] -> Q ; epilogue: cs[v] = colsums(Q)
__global__ void __launch_bounds__(1024) k_qr(int qs){
    __shared__ float sb[512];
    int v = blockIdx.x;
    float* Q = qs ? g_Zb[v] : g_Qb[v];
    int tid = threadIdx.x;
    float vv[4][6];
    #pragma unroll
    for (int rr = 0; rr < 4; rr++){ int i = tid + rr*1024;
        #pragma unroll
        for (int j = 0; j < 6; j++) vv[rr][j] = g_Y[v][i*6+j]; }
    for (int j = 0; j < 6; j++){
        for (int pass = 0; pass < 2 && j > 0; pass++){
            float h[5];
            for (int q = 0; q < j; q++){
                float s = 0;
                #pragma unroll
                for (int rr = 0; rr < 4; rr++) s += vv[rr][q]*vv[rr][j];
                h[q] = s;
            }
            bred(h, j, sb);
            for (int q = 0; q < j; q++)
                #pragma unroll
                for (int rr = 0; rr < 4; rr++) vv[rr][j] -= h[q]*vv[rr][q];
        }
        float n2 = 0;
        #pragma unroll
        for (int rr = 0; rr < 4; rr++) n2 += vv[rr][j]*vv[rr][j];
        bred(&n2, 1, sb);
        float sc = 1.f/sqrtf(fmaxf(n2, 1e-30f));
        #pragma unroll
        for (int rr = 0; rr < 4; rr++) vv[rr][j] *= sc;
    }
    float p[6] = {0,0,0,0,0,0};
    #pragma unroll
    for (int rr = 0; rr < 4; rr++){ int i = tid + rr*1024;
        #pragma unroll
        for (int j = 0; j < 6; j++){ Q[i*6+j] = vv[rr][j]; p[j] += vv[rr][j]; } }
    bred(p, 6, sb);
    if (tid < 6) g_cs[v][tid] = p[tid];
}

// G = Y (already includes eps); M6 = G^T G; Jacobi eigen; sorted eigvecs -> U6
__global__ void __launch_bounds__(1024) k_finB(){
    __shared__ float sb[512];
    int v = blockIdx.x, tid = threadIdx.x;
    float g[4][6];
    #pragma unroll
    for (int rr = 0; rr < 4; rr++){ int i = tid + rr*1024;
        #pragma unroll
        for (int j = 0; j < 6; j++) g[rr][j] = g_Y[v][i*6+j]; }
    float p[21]; int id = 0;
    for (int a = 0; a < 6; a++)
        for (int b = a; b < 6; b++){
            float s = 0;
            #pragma unroll
            for (int rr = 0; rr < 4; rr++) s += g[rr][a]*g[rr][b];
            p[id++] = s;
        }
    bred(p, 6, sb); bred(p+6, 6, sb); bred(p+12, 6, sb); bred(p+18, 3, sb);
    if (tid == 0){
        double A[6][6], Vv[6][6]; id = 0;
        for (int a = 0; a < 6; a++) for (int b = a; b < 6; b++){ A[a][b] = p[id]; A[b][a] = p[id]; id++; }
        for (int a = 0; a < 6; a++) for (int b = 0; b < 6; b++) Vv[a][b] = (a==b) ? 1.0 : 0.0;
        for (int sw = 0; sw < 30; sw++)
            for (int pp = 0; pp < 5; pp++) for (int q = pp+1; q < 6; q++){
                double apq = A[pp][q]; if (fabs(apq) < 1e-30) continue;
                double tau = (A[q][q]-A[pp][pp])/(2.0*apq);
                double t = (tau >= 0 ? 1.0 : -1.0)/(fabs(tau)+sqrt(1.0+tau*tau));
                double c = 1.0/sqrt(1.0+t*t), s = t*c;
                for (int i = 0; i < 6; i++){ double a1=A[i][pp],a2=A[i][q]; A[i][pp]=c*a1-s*a2; A[i][q]=s*a1+c*a2; }
                for (int i = 0; i < 6; i++){ double a1=A[pp][i],a2=A[q][i]; A[pp][i]=c*a1-s*a2; A[q][i]=s*a1+c*a2; }
                for (int i = 0; i < 6; i++){ double a1=Vv[i][pp],a2=Vv[i][q]; Vv[i][pp]=c*a1-s*a2; Vv[i][q]=s*a1+c*a2; }
            }
        int ord[6] = {0,1,2,3,4,5};
        for (int a = 0; a < 6; a++) for (int b = a+1; b < 6; b++)
            if (A[ord[b]][ord[b]] > A[ord[a]][ord[a]]){ int t2 = ord[a]; ord[a] = ord[b]; ord[b] = t2; }
        for (int kk = 0; kk < 6; kk++) for (int j = 0; j < 6; j++) g_U6[v][j*6+kk] = (float)Vv[j][ord[kk]];
    }
}

// V = G @ U6 ; init c=1 ; prep k=0 leaf (u = V[:,0]) + eps-sums
__global__ void __launch_bounds__(1024) k_compVprep(){
    __shared__ float sb[512];
    int v = blockIdx.x, tid = threadIdx.x;
    const float* rr_ = g_r + v*NV;
    float s2[2] = {0,0};
    #pragma unroll
    for (int rr = 0; rr < 4; rr++){
        int i = tid + rr*1024;
        float gr[6];
        #pragma unroll
        for (int j = 0; j < 6; j++) gr[j] = g_Y[v][i*6+j];
        #pragma unroll
        for (int kk = 0; kk < 6; kk++){
            float s = 0;
            #pragma unroll
            for (int j = 0; j < 6; j++) s += gr[j]*g_U6[v][j*6+kk];
            g_V[v][i*6+kk] = s;
        }
        float u = g_V[v][i*6+0];
        g_UU[v][i] = u;
        if (v == 0) g_c[i] = 1.f;
        s2[0] += u; s2[1] += rr_[i]*u;
    }
    bred(s2, 2, sb);
    if (tid == 0){ g_sm[v][0] = s2[0]; g_sm[v][1] = s2[1]; }
}

// ---------------- nuclear loss (aa0 matvec via two CSR gathers) ----------------
__global__ void k_gT(const float* __restrict__ w1, const float* __restrict__ w2){
    int n = (blockIdx.x*blockDim.x + threadIdx.x) >> 5, lane = threadIdx.x & 31;
    int v = blockIdx.y;
    if (n >= NV) return;
    const float* w = v ? w2 : w1;
    float acc = 0;
    int p1 = g_startd[n+1];
    for (int p = g_startd[n] + lane; p < p1; p += 32)
        acc += w[g_adj_d_eid[p]] * g_UU[v][g_adj_d_src[p]];
    acc = wsum(acc);
    if (lane == 0) g_TT[v][n] = acc;
}

__global__ void k_gZ(const float* __restrict__ w1, const float* __restrict__ w2){
    int n = (blockIdx.x*blockDim.x + threadIdx.x) >> 5, lane = threadIdx.x & 31;
    int v = blockIdx.y;
    if (n >= NV) return;
    const float* w = v ? w2 : w1;
    float acc = 0;
    int p1 = g_starts[n+1];
    for (int p = g_starts[n] + lane; p < p1; p += 32)
        acc += w[g_adj_s_eid[p]] * g_TT[v][g_adj_s_dst[p]];
    acc = wsum(acc);
    if (lane == 0) g_ZZ[v][n] = acc;
}

// vi = normalize(masked/deflated aa @ prev); prepare second-apply leaf + sums
__global__ void __launch_bounds__(1024) k_mid(int nd){
    __shared__ float sb[512];
    int v = blockIdx.x, tid = threadIdx.x;
    const float* rr_ = g_r + v*NV;
    float s0 = g_sm[v][0], s1v = g_sm[v][1];
    float pv[4]; float n2 = 0;
    #pragma unroll
    for (int rr = 0; rr < 4; rr++){
        int i = tid + rr*1024;
        float z = g_ZZ[v][i] + EPS*(s0*rr_[i] + s1v + EPSN*s0);
        if (v == 0) z *= g_c[i];
        pv[rr] = z; n2 += z*z;
    }
    bred(&n2, 1, sb);
    float inv = 1.f/sqrtf(fmaxf(n2, 1e-30f));
    #pragma unroll
    for (int rr = 0; rr < 4; rr++){ pv[rr] *= inv; g_vi[v][tid + rr*1024] = pv[rr]; }
    float u[4];
    if (v == 0){
        #pragma unroll
        for (int rr = 0; rr < 4; rr++) u[rr] = pv[rr]*g_c[tid + rr*1024];
    } else {
        #pragma unroll
        for (int rr = 0; rr < 4; rr++) u[rr] = pv[rr];
        for (int j = nd-1; j >= 0; j--){
            float dd = 0;
            #pragma unroll
            for (int rr = 0; rr < 4; rr++) dd += g_D[j][tid+rr*1024]*u[rr];
            bred(&dd, 1, sb);
            #pragma unroll
            for (int rr = 0; rr < 4; rr++) u[rr] -= dd*g_D[j][tid+rr*1024];
        }
    }
    float s2[2] = {0,0};
    #pragma unroll
    for (int rr = 0; rr < 4; rr++){
        int i = tid + rr*1024;
        g_UU[v][i] = u[rr];
        s2[0] += u[rr]; s2[1] += rr_[i]*u[rr];
    }
    bred(s2, 2, sb);
    if (tid == 0){ g_sm[v][0] = s2[0]; g_sm[v][1] = s2[1]; }
}

// fin(k): loss term + deflation update ; prep(k+1)
__global__ void __launch_bounds__(1024) k_finprep(int k, int knext, int ndp){
    __shared__ float sb[512];
    int v = blockIdx.x, tid = threadIdx.x;
    const float* rr_ = g_r + v*NV;
    float s0 = g_sm[v][0], s1v = g_sm[v][1];
    float s2[2] = {0,0};
    #pragma unroll
    for (int rr = 0; rr < 4; rr++){
        int i = tid + rr*1024;
        float z = g_ZZ[v][i] + EPS*(s0*rr_[i] + s1v + EPSN*s0);
        float vi = g_vi[v][i];
        float lhs = (v == 0) ? g_UU[v][i] : vi;   // v=0: leaf = c*vi
        s2[0] += lhs*z; s2[1] += vi*vi;
    }
    bred(s2, 2, sb);
    if (tid == 0) g_nuc[v] += sqrtf(fabsf(s2[0]/s2[1]));
    // deflation update after loss (reference deflates at end of steps k=2..5; k=5 unused)
    if (k >= 2 && k <= 4){
        if (v == 0){
            #pragma unroll
            for (int rr = 0; rr < 4; rr++){ int i = tid + rr*1024; g_c[i] *= g_vi[0][i]; }
        } else {
            #pragma unroll
            for (int rr = 0; rr < 4; rr++){ int i = tid + rr*1024; g_D[k-2][i] = g_vi[1][i]; }
        }
    }
    if (knext < 0) return;
    // prep next k
    float u[4];
    if (v == 0){
        #pragma unroll
        for (int rr = 0; rr < 4; rr++){ int i = tid + rr*1024; u[rr] = g_c[i]*g_V[0][i*6 + knext]; }
    } else {
        #pragma unroll
        for (int rr = 0; rr < 4; rr++) u[rr] = g_V[1][(tid+rr*1024)*6 + knext];
        for (int j = ndp-1; j >= 0; j--){
            float dd = 0;
            #pragma unroll
            for (int rr = 0; rr < 4; rr++) dd += g_D[j][tid+rr*1024]*u[rr];
            bred(&dd, 1, sb);
            #pragma unroll
            for (int rr = 0; rr < 4; rr++) u[rr] -= dd*g_D[j][tid+rr*1024];
        }
    }
    float s2b[2] = {0,0};
    #pragma unroll
    for (int rr = 0; rr < 4; rr++){
        int i = tid + rr*1024;
        g_UU[v][i] = u[rr];
        s2b[0] += u[rr]; s2b[1] += rr_[i]*u[rr];
    }
    bred(s2b, 2, sb);
    if (tid == 0){ g_sm[v][0] = s2b[0]; g_sm[v][1] = s2b[1]; }
}

__global__ void k_final(float* loss, float* calib){
    double E = (double)EV;
    double c1 = g_ds[1]/E - (g_ds[0]/E)*(g_ds[0]/E);
    double c2 = g_ds[3]/E - (g_ds[2]/E)*(g_ds[2]/E);
    *loss  = (float)(0.01*(c1+c2) + 0.01*((double)g_nuc[0] + (double)g_nuc[1]));
    *calib = (float)(g_ds[6]/(double)NV);
}

extern "C" void kernel_launch(void* const* d_in, const int* in_sizes, int n_in,
                              void* d_out, int out_size){
    const float* x     = (const float*)d_in[0];
    const int*   ei    = (const int*)d_in[1];
    const int*   src   = ei;
    const int*   dst   = ei + EV;
    const float* gcn1b = (const float*)d_in[3];
    const float* gcn2b = (const float*)d_in[5];
    const float* p1b1  = (const float*)d_in[7];
    const float* p1w2  = (const float*)d_in[8];
    const float* p1b2  = (const float*)d_in[9];
    const float* p2b1  = (const float*)d_in[11];
    const float* p2w2  = (const float*)d_in[12];
    const float* p2b2  = (const float*)d_in[13];
    const float* om1   = (const float*)d_in[14];
    const float* om2   = (const float*)d_in[15];

    float* out   = (float*)d_out;
    float* lsm   = out;
    float* sm    = out + NV*16;
    float* loss  = out + 2*NV*16;
    float* s1    = out + 2*NV*16 + 1;
    float* s2    = s1 + EV;
    float* calib = s2 + EV;

    k_init<<<32,256>>>();
    k_hist<<<EV/256,256>>>(src, dst);
    k_scan<<<1,1024>>>();
    k_csr<<<EV/256,256>>>(src, dst);
    k_catW<<<(512*128+255)/256,256>>>((const float*)d_in[2], (const float*)d_in[6], 0);
    k_catW<<<(64*48+255)/256,256>>>((const float*)d_in[4], (const float*)d_in[10], 1);
    k_gemm<<<dim3(2,64),256>>>(x, 0);
    k_gate1<<<EV/8,256>>>(p1b1, p1w2, p1b2, src, dst, s1);
    k_sumS<<<64,256>>>(s1, 0);
    k_gcn0<<<512,256>>>(gcn1b, s1);
    k_gemm<<<dim3(1,64),256>>>(x, 1);
    k_gate2<<<EV/8,256>>>(p2b1, p2w2, p2b2, src, dst, s2);
    k_sumS<<<64,256>>>(s2, 2);
    k_gcn1<<<512,256>>>(gcn2b, s2);
    k_softmax<<<16,256>>>(lsm, sm);

    // randomized SVD (both variants batched: blockIdx.y / blockIdx.x = variant)
    dim3 gg(512,2);
    k_csext<<<2,1024>>>(om1, om2);
    k_g6<<<gg,256>>>(om1, om2, 2, 0, s1, s2);
    k_qr<<<2,1024>>>(0);
    for (int it = 0; it < 2; it++){
        k_g6<<<gg,256>>>(om1, om2, 0, 1, s1, s2);
        k_qr<<<2,1024>>>(1);
        k_g6<<<gg,256>>>(om1, om2, 1, 0, s1, s2);
        k_qr<<<2,1024>>>(0);
    }
    k_g6<<<gg,256>>>(om1, om2, 0, 1, s1, s2);
    k_finB<<<2,1024>>>();
    k_compVprep<<<2,1024>>>();

    // nuclear loss: 6 deflation steps, both variants per launch
    for (int k = 0; k < 6; k++){
        int nd = k - 2; if (nd < 0) nd = 0; if (nd > 3) nd = 3;
        k_gT<<<gg,256>>>(s1, s2);
        k_gZ<<<gg,256>>>(s1, s2);
        k_mid<<<2,1024>>>(nd);
        k_gT<<<gg,256>>>(s1, s2);
        k_gZ<<<gg,256>>>(s1, s2);
        int knext = (k < 5) ? k+1 : -1;
        int ndp = 0;
        if (knext >= 0){ ndp = knext - 2; if (ndp < 0) ndp = 0; if (ndp > 3) ndp = 3; }
        k_finprep<<<2,1024>>>(k, knext, ndp);
    }
    k_final<<<1,1>>>(loss, calib);
}